// round 17
// baseline (speedup 1.0000x reference)
#include <cuda_runtime.h>
#include <cuda_fp16.h>
#include <math.h>

#define D_RF   2048
#define NOBS   20000
#define N_ST   1024
#define N_ACT  64
#define SDIM   256
#define DECAYF 0.9f
#define BETA_O 1.0f
#define BETA_S 1.0f

// ---- scratch (static device globals: no allocation) ----
__device__ __half2 g_phi[D_RF * N_ST];  // packed (cos, sin) pairs, 8 MB
__device__ float g_s0re[D_RF], g_s0im[D_RF];
__device__ float g_s2re[D_RF], g_s2im[D_RF];
__device__ float g_score[N_ST];
__device__ float g_dotRe;
__device__ float g_obsacc[NOBS];
__device__ float g_sumf;

// ---- packed f32x2 helpers (sm_103a; ptxas never auto-fuses FFMA2) ----
__device__ __forceinline__ unsigned long long pack2(float lo, float hi) {
    unsigned long long r;
    asm("mov.b64 %0, {%1, %2};" : "=l"(r) : "f"(lo), "f"(hi));
    return r;
}
__device__ __forceinline__ void unpack2(unsigned long long v, float& lo, float& hi) {
    asm("mov.b64 {%0, %1}, %2;" : "=f"(lo), "=f"(hi) : "l"(v));
}
__device__ __forceinline__ void fma2(unsigned long long& d,
                                     unsigned long long a, unsigned long long b) {
    asm("fma.rn.f32x2 %0, %1, %2, %0;" : "+l"(d) : "l"(a), "l"(b));
}

// ---- FMA-pipe sincos (keeps MUFU pressure off the epilogue) ----
__device__ __forceinline__ void fast_sincos(float x, float& s, float& c) {
    const float TWO_OVER_PI = 0.63661975f;
    const float PIO2_HI    = 1.5707963705062866f;
    const float PIO2_LO    = -4.3711388e-8f;
    float qf = rintf(x * TWO_OVER_PI);
    float r  = fmaf(qf, -PIO2_HI, x);
    r        = fmaf(qf, -PIO2_LO, r);
    const int iq = (int)qf;
    const float r2 = r * r;
    float ps = -1.9841270e-4f;
    ps = fmaf(ps, r2, 8.3333338e-3f);
    ps = fmaf(ps, r2, -0.16666667f);
    const float sp = fmaf(ps * r2, r, r);
    float pc = 2.4801587e-5f;
    pc = fmaf(pc, r2, -1.3888889e-3f);
    pc = fmaf(pc, r2, 4.1666668e-2f);
    pc = fmaf(pc, r2, -0.5f);
    const float cp = fmaf(pc, r2, 1.0f);
    const bool swap = (iq & 1) != 0;
    float ss = swap ? cp : sp;
    float cc = swap ? sp : cp;
    if (iq & 2)       ss = -ss;
    if ((iq + 1) & 2) cc = -cc;
    s = ss; c = cc;
}

// ============================================================
// GEMM phase: one 64x64 phi tile (f32x2 micro-kernel), epilogue
// stores packed half2(cos,sin).
// ============================================================
__device__ __forceinline__ void gemm_phase(
    int tile, int tid, float (*Ws)[68], float (*Qs)[68],
    const float* __restrict__ W, const float* __restrict__ Q)
{
    const int td = tile >> 4, ts = tile & 15;
    const int d0 = td * 64, s0 = ts * 64;
    const int tx = tid & 15, ty = tid >> 4;

    unsigned long long acc2[4][2];
    #pragma unroll
    for (int i = 0; i < 4; i++) { acc2[i][0] = 0ull; acc2[i][1] = 0ull; }

    const int wdl = tid >> 2, wkq = (tid & 3) * 4;
    const int qk  = tid >> 4, qsq = (tid & 15) * 4;

    for (int k0 = 0; k0 < SDIM; k0 += 16) {
        const float4 w4 = *(const float4*)&W[(size_t)(d0 + wdl) * SDIM + k0 + wkq];
        const float4 q4 = *(const float4*)&Q[(size_t)(k0 + qk) * N_ST + s0 + qsq];
        __syncthreads();
        Ws[wkq + 0][wdl] = w4.x; Ws[wkq + 1][wdl] = w4.y;
        Ws[wkq + 2][wdl] = w4.z; Ws[wkq + 3][wdl] = w4.w;
        *(float4*)&Qs[qk][qsq] = q4;
        __syncthreads();
        #pragma unroll
        for (int k = 0; k < 16; k++) {
            const float4 wv = *(float4*)&Ws[k][ty * 4];
            const float4 qv = *(float4*)&Qs[k][tx * 4];
            const unsigned long long q01 = pack2(qv.x, qv.y);
            const unsigned long long q23 = pack2(qv.z, qv.w);
            unsigned long long wp;
            wp = pack2(wv.x, wv.x); fma2(acc2[0][0], wp, q01); fma2(acc2[0][1], wp, q23);
            wp = pack2(wv.y, wv.y); fma2(acc2[1][0], wp, q01); fma2(acc2[1][1], wp, q23);
            wp = pack2(wv.z, wv.z); fma2(acc2[2][0], wp, q01); fma2(acc2[2][1], wp, q23);
            wp = pack2(wv.w, wv.w); fma2(acc2[3][0], wp, q01); fma2(acc2[3][1], wp, q23);
        }
    }
    #pragma unroll
    for (int i = 0; i < 4; i++) {
        float a0, a1, a2, a3;
        unpack2(acc2[i][0], a0, a1);
        unpack2(acc2[i][1], a2, a3);
        float c[4], s[4];
        fast_sincos(a0, s[0], c[0]);
        fast_sincos(a1, s[1], c[1]);
        fast_sincos(a2, s[2], c[2]);
        fast_sincos(a3, s[3], c[3]);
        __half2 hp[4];
        hp[0] = __floats2half2_rn(c[0], s[0]);
        hp[1] = __floats2half2_rn(c[1], s[1]);
        hp[2] = __floats2half2_rn(c[2], s[2]);
        hp[3] = __floats2half2_rn(c[3], s[3]);
        const size_t base = (size_t)(d0 + ty * 4 + i) * N_ST + s0 + tx * 4;
        *(float4*)&g_phi[base] = *(float4*)hp;
    }
    __syncthreads();   // quiesce smem before the other phase reuses it
}

// ============================================================
// M phase: state0 for rows 4*mb..4*mb+3 (+ zero-init side duties)
// ============================================================
__device__ __forceinline__ void m_phase(
    int mb, int tid, float* sh,
    const float* __restrict__ M_re, const float* __restrict__ M_im,
    const float* __restrict__ obs)
{
    const int d0 = mb * 4;
    if (mb < 80) { int o = mb * 256 + tid; if (o < NOBS) g_obsacc[o] = 0.f; }
    if (mb < 4)  g_score[mb * 256 + tid] = 0.f;
    if (mb == 0 && tid == 0) { g_dotRe = 0.f; g_sumf = 0.f; }

    const float4* mr = (const float4*)M_re;
    const float4* mi = (const float4*)M_im;
    const float4* ob = (const float4*)obs;

    float are[4] = {0.f, 0.f, 0.f, 0.f};
    float aim[4] = {0.f, 0.f, 0.f, 0.f};

    for (int i = tid; i < NOBS / 4; i += 256) {
        const float4 o4 = ob[i];
        float4 r[4], m4[4];
        #pragma unroll
        for (int rr = 0; rr < 4; rr++) {
            const size_t row = (size_t)(d0 + rr) * (NOBS / 4) + i;
            r[rr]  = __ldcs(&mr[row]);
            m4[rr] = __ldcs(&mi[row]);
        }
        #pragma unroll
        for (int rr = 0; rr < 4; rr++) {
            are[rr] = fmaf(r[rr].x,  o4.x, fmaf(r[rr].y,  o4.y,
                      fmaf(r[rr].z,  o4.z, fmaf(r[rr].w,  o4.w, are[rr]))));
            aim[rr] = fmaf(m4[rr].x, o4.x, fmaf(m4[rr].y, o4.y,
                      fmaf(m4[rr].z, o4.z, fmaf(m4[rr].w, o4.w, aim[rr]))));
        }
    }
    #pragma unroll
    for (int rr = 0; rr < 4; rr++) {
        sh[(rr * 2 + 0) * 256 + tid] = are[rr];
        sh[(rr * 2 + 1) * 256 + tid] = aim[rr];
    }
    __syncthreads();
    const int w = tid >> 5, l = tid & 31;
    float v = 0.f;
    #pragma unroll
    for (int k = 0; k < 8; k++) v += sh[w * 256 + l + k * 32];
    #pragma unroll
    for (int off = 16; off > 0; off >>= 1) v += __shfl_down_sync(~0u, v, off);
    if (l == 0) {
        const int rr = w >> 1;
        if ((w & 1) == 0) g_s0re[d0 + rr] = v;
        else              g_s0im[d0 + rr] = v;
    }
    __syncthreads();   // quiesce smem before the other phase reuses it
}

// ============================================================
// Kernel AB: 512 blocks (one wave at 4/SM); GEMM+M sequential per
// block. Phase order selected by ((b>>1)&1): co-resident bids on one
// SM are {b, b+148, b+296, b+444} (bid%148 placement), and 148 is
// even, so bid-parity is CONSTANT per SM — (b>>1)&1 flips between
// b and b+148, giving every SM 2 GEMM-first + 2 M-first blocks.
// ============================================================
__global__ void __launch_bounds__(256, 4) k_ab(
    const float* __restrict__ W, const float* __restrict__ Q,
    const float* __restrict__ M_re, const float* __restrict__ M_im,
    const float* __restrict__ obs)
{
    __shared__ float sh[2 * 16 * 68];
    const int b   = blockIdx.x;
    const int tid = threadIdx.x;
    float (*Ws)[68] = (float(*)[68])sh;
    float (*Qs)[68] = (float(*)[68])(sh + 16 * 68);

    if (((b >> 1) & 1) == 0) {
        gemm_phase(b, tid, Ws, Qs, W, Q);
        m_phase(b, tid, sh, M_re, M_im, obs);
    } else {
        m_phase(b, tid, sh, M_re, M_im, obs);
        gemm_phase(b, tid, Ws, Qs, W, Q);
    }
}

// ============================================================
// Kernel SC (fused state1 + score): 256 blocks x 256 threads,
// 8 rows/block, half2 table loads.  [R16]
// ============================================================
__global__ void __launch_bounds__(256) k_score_impl(
    const float* __restrict__ V, const float* __restrict__ W,
    const float* __restrict__ action)
{
    __shared__ float vs[SDIM];
    __shared__ float s1r[8], s1i[8];
    const int tid = threadIdx.x;
    const int d0  = blockIdx.x * 8;
    const int w = tid >> 5, l = tid & 31;

    {
        float a = 0.f;
        const float* vr = V + tid * N_ACT;
        #pragma unroll 8
        for (int k = 0; k < N_ACT; k++) a = fmaf(vr[k], action[k], a);
        vs[tid] = a;
    }
    __syncthreads();

    {
        const int d = d0 + w;
        const float* wr = W + (size_t)d * SDIM;
        float t = 0.f;
        #pragma unroll
        for (int k = l; k < SDIM; k += 32) t = fmaf(wr[k], vs[k], t);
        #pragma unroll
        for (int off = 16; off > 0; off >>= 1) t += __shfl_down_sync(~0u, t, off);
        if (l == 0) {
            float sn, cs;
            sincosf(t, &sn, &cs);
            const float a = g_s0re[d], bb = g_s0im[d];
            s1r[w] = a * cs - bb * sn;
            s1i[w] = a * sn + bb * cs;
        }
    }
    __syncthreads();

    float4 acc = make_float4(0.f, 0.f, 0.f, 0.f);
    #pragma unroll
    for (int dd = 0; dd < 8; dd++) {
        const size_t row = (size_t)(d0 + dd) * N_ST + tid * 4;
        const float4 p4 = __ldcs((const float4*)&g_phi[row]);   // 4 half2 pairs
        const __half2* hp = (const __half2*)&p4;
        const float2 p0 = __half22float2(hp[0]);
        const float2 p1 = __half22float2(hp[1]);
        const float2 p2 = __half22float2(hp[2]);
        const float2 p3 = __half22float2(hp[3]);
        const float a = s1r[dd], bb = s1i[dd];
        acc.x = fmaf(p0.x, a, fmaf(p0.y, bb, acc.x));
        acc.y = fmaf(p1.x, a, fmaf(p1.y, bb, acc.y));
        acc.z = fmaf(p2.x, a, fmaf(p2.y, bb, acc.z));
        acc.w = fmaf(p3.x, a, fmaf(p3.y, bb, acc.w));
    }
    const float sc = BETA_S / (float)D_RF;
    atomicAdd(&g_score[tid * 4 + 0], acc.x * sc);
    atomicAdd(&g_score[tid * 4 + 1], acc.y * sc);
    atomicAdd(&g_score[tid * 4 + 2], acc.z * sc);
    atomicAdd(&g_score[tid * 4 + 3], acc.w * sc);
}

// ============================================================
// Kernel F (fused softmax + state2): 512 blocks x 256 threads,
// half2 table loads.  [R16]
// ============================================================
__global__ void __launch_bounds__(256) k_state2()
{
    __shared__ __align__(16) float ws[N_ST];
    __shared__ float red[9];
    __shared__ float2 parts[8];
    const int tid = threadIdx.x;
    const int w = tid >> 5, l = tid & 31;

    float v0 = g_score[tid], v1 = g_score[tid + 256],
          v2 = g_score[tid + 512], v3 = g_score[tid + 768];
    float m = fmaxf(fmaxf(v0, v1), fmaxf(v2, v3));
    #pragma unroll
    for (int off = 16; off > 0; off >>= 1) m = fmaxf(m, __shfl_xor_sync(~0u, m, off));
    if (l == 0) red[w] = m;
    __syncthreads();
    if (tid < 32) {
        float t = (tid < 8) ? red[tid] : -1e30f;
        #pragma unroll
        for (int off = 4; off > 0; off >>= 1) t = fmaxf(t, __shfl_xor_sync(~0u, t, off));
        if (tid == 0) red[8] = t;
    }
    __syncthreads();
    const float mx = red[8];
    float e0 = __expf(v0 - mx), e1 = __expf(v1 - mx),
          e2 = __expf(v2 - mx), e3 = __expf(v3 - mx);
    float s = e0 + e1 + e2 + e3;
    __syncthreads();
    #pragma unroll
    for (int off = 16; off > 0; off >>= 1) s += __shfl_xor_sync(~0u, s, off);
    if (l == 0) red[w] = s;
    __syncthreads();
    if (tid < 32) {
        float t = (tid < 8) ? red[tid] : 0.f;
        #pragma unroll
        for (int off = 4; off > 0; off >>= 1) t += __shfl_xor_sync(~0u, t, off);
        if (tid == 0) red[8] = t;
    }
    __syncthreads();
    const float inv = 1.f / red[8];
    ws[tid]       = e0 * inv;
    ws[tid + 256] = e1 * inv;
    ws[tid + 512] = e2 * inv;
    ws[tid + 768] = e3 * inv;
    __syncthreads();

    const int d    = blockIdx.x * 4 + (w >> 1);
    const int half = w & 1;
    const __half2* pr = g_phi + (size_t)d * N_ST;
    float ar = 0.f, ai = 0.f;
    #pragma unroll
    for (int j = 0; j < 4; j++) {
        const int s4 = half * 512 + (l + j * 32) * 4;
        const float4 p4 = __ldcs((const float4*)&pr[s4]);
        const __half2* hp = (const __half2*)&p4;
        const float4 w4 = *(const float4*)&ws[s4];
        const float2 p0 = __half22float2(hp[0]);
        const float2 p1 = __half22float2(hp[1]);
        const float2 p2 = __half22float2(hp[2]);
        const float2 p3 = __half22float2(hp[3]);
        ar = fmaf(p0.x, w4.x, fmaf(p1.x, w4.y, fmaf(p2.x, w4.z, fmaf(p3.x, w4.w, ar))));
        ai = fmaf(p0.y, w4.x, fmaf(p1.y, w4.y, fmaf(p2.y, w4.z, fmaf(p3.y, w4.w, ai))));
    }
    #pragma unroll
    for (int off = 16; off > 0; off >>= 1) {
        ar += __shfl_down_sync(~0u, ar, off);
        ai += __shfl_down_sync(~0u, ai, off);
    }
    if (l == 0) parts[w] = make_float2(ar, ai);
    __syncthreads();
    if (tid < 4) {
        const int dd = blockIdx.x * 4 + tid;
        const float rr = parts[tid * 2].x + parts[tid * 2 + 1].x;
        const float ii = parts[tid * 2].y + parts[tid * 2 + 1].y;
        g_s2re[dd] = rr; g_s2im[dd] = ii;
        atomicAdd(&g_dotRe, g_s0re[dd] * rr + g_s0im[dd] * ii);
    }
}

// ============================================================
// Kernel H: obsacc[o] += sum_d M_re[d,o]*s2re[d] + M_im[d,o]*s2im[d]
// grid 1280: 20 o-chunks x 64 d-chunks (32 rows)   [R16-exact]
// ============================================================
__global__ void __launch_bounds__(256) k_obs(
    const float* __restrict__ M_re, const float* __restrict__ M_im)
{
    __shared__ float s2r[32], s2i[32];
    const int oc = blockIdx.x % 20, dc = blockIdx.x / 20;
    const int tid = threadIdx.x;
    const int d0 = dc * 32;
    if (tid < 32) { s2r[tid] = g_s2re[d0 + tid]; s2i[tid] = g_s2im[d0 + tid]; }
    __syncthreads();
    const int o4 = oc * 256 + tid;
    if (o4 >= NOBS / 4) return;
    const float4* mr = (const float4*)M_re;
    const float4* mi = (const float4*)M_im;
    float4 acc = make_float4(0.f, 0.f, 0.f, 0.f);
    #pragma unroll
    for (int d8 = 0; d8 < 32; d8 += 8) {
        float4 r[8], im[8];
        #pragma unroll
        for (int j = 0; j < 8; j++) {
            const size_t row = (size_t)(d0 + d8 + j) * (NOBS / 4) + o4;
            r[j]  = __ldcs(&mr[row]);
            im[j] = __ldcs(&mi[row]);
        }
        #pragma unroll
        for (int j = 0; j < 8; j++) {
            const float a = s2r[d8 + j], b = s2i[d8 + j];
            acc.x = fmaf(r[j].x, a, fmaf(im[j].x, b, acc.x));
            acc.y = fmaf(r[j].y, a, fmaf(im[j].y, b, acc.y));
            acc.z = fmaf(r[j].z, a, fmaf(im[j].z, b, acc.z));
            acc.w = fmaf(r[j].w, a, fmaf(im[j].w, b, acc.w));
        }
    }
    atomicAdd(&g_obsacc[o4 * 4 + 0], acc.x);
    atomicAdd(&g_obsacc[o4 * 4 + 1], acc.y);
    atomicAdd(&g_obsacc[o4 * 4 + 2], acc.z);
    atomicAdd(&g_obsacc[o4 * 4 + 3], acc.w);
}

// ============================================================
// Kernel SUM: e = exp(logit); store e to out, atomic block sums. [R16]
// ============================================================
__global__ void __launch_bounds__(1024) k_sum(
    const float* __restrict__ obs, float* __restrict__ out)
{
    __shared__ float red[32];
    const int tid = threadIdx.x;
    const int gi  = blockIdx.x * 1024 + tid;
    const int w = tid >> 5, l = tid & 31;

    float e = 0.f;
    if (gi < NOBS) {
        const float scale = BETA_O / (float)D_RF;
        const float v = scale * (DECAYF * g_obsacc[gi] + obs[gi] * g_dotRe);
        e = __expf(v);
        out[gi] = e;
    }
    float s = e;
    #pragma unroll
    for (int off = 16; off > 0; off >>= 1) s += __shfl_xor_sync(~0u, s, off);
    if (l == 0) red[w] = s;
    __syncthreads();
    if (tid < 32) {
        float t = red[tid];
        #pragma unroll
        for (int off = 16; off > 0; off >>= 1) t += __shfl_xor_sync(~0u, t, off);
        if (tid == 0) atomicAdd(&g_sumf, t);
    }
}

// ============================================================
// Kernel NORM: out[i] /= sum. 20 blocks x 1024 threads. [R16]
// ============================================================
__global__ void __launch_bounds__(1024) k_norm(float* __restrict__ out)
{
    const int gi = blockIdx.x * 1024 + threadIdx.x;
    if (gi < NOBS) out[gi] *= (1.f / g_sumf);
}

// ============================================================
extern "C" void kernel_launch(void* const* d_in, const int* in_sizes, int n_in,
                              void* d_out, int out_size)
{
    const float* Q      = (const float*)d_in[0];
    const float* V      = (const float*)d_in[1];
    const float* W      = (const float*)d_in[2];
    const float* M_re   = (const float*)d_in[3];
    const float* M_im   = (const float*)d_in[4];
    const float* obs    = (const float*)d_in[5];
    const float* action = (const float*)d_in[6];
    float* out = (float*)d_out;

    k_ab<<<512, 256>>>(W, Q, M_re, M_im, obs);    // per-SM mixed phases ((b>>1)&1)
    k_score_impl<<<256, 256>>>(V, W, action);     // state1 (smem) + score partials
    k_state2<<<512, 256>>>();                     // softmax + state2 + dotRe
    k_obs<<<1280, 256>>>(M_re, M_im);             // M^T . conj(state2) partials
    k_sum<<<20, 1024>>>(obs, out);                // logits + exp + global sum
    k_norm<<<20, 1024>>>(out);                    // normalize
}